// round 1
// baseline (speedup 1.0000x reference)
#include <cuda_runtime.h>
#include <cstdint>
#include <math.h>

#define BATCH 16
#define SEQ   512
#define DC    1024
#define DP    64
#define NT    8
#define DH    4096
#define NTOK  (BATCH*SEQ)

#define BM 128
#define BN 64
#define BK 32
#define MAXMB 72   // sum over tiles of ceil(cnt/BM) <= 64 + 8

// ---- scratch (static __device__: allocation-free per harness rules) ----
__device__ int   g_tile_of[NTOK];
__device__ int   g_counts[NT];
__device__ int   g_offsets[NT];
__device__ int   g_cursor[NT];
__device__ int   g_perm[NTOK];
__device__ float g_h[(size_t)NTOK * DH];   // 128 MB intermediate

__device__ __forceinline__ uint32_t f2tf32(float f) {
    uint32_t r;
    asm("cvt.rna.tf32.f32 %0, %1;" : "=r"(r) : "f"(f));
    return r;
}

__device__ __forceinline__ void mma8(float* c, const uint32_t* a, const uint32_t* b) {
    asm volatile(
        "mma.sync.aligned.m16n8k8.row.col.f32.tf32.tf32.f32 "
        "{%0,%1,%2,%3}, {%4,%5,%6,%7}, {%8,%9}, {%0,%1,%2,%3};\n"
        : "+f"(c[0]), "+f"(c[1]), "+f"(c[2]), "+f"(c[3])
        : "r"(a[0]), "r"(a[1]), "r"(a[2]), "r"(a[3]), "r"(b[0]), "r"(b[1]));
}

// ---------------- routing ----------------
__global__ void k_init() {
    if (threadIdx.x < NT) g_counts[threadIdx.x] = 0;
}

__global__ void k_route(const float* __restrict__ x, const float* __restrict__ pe,
                        const float* __restrict__ pwp, const float* __restrict__ cwp,
                        const float* __restrict__ ps, const float* __restrict__ cs) {
    __shared__ float s_cs[NT * DC];
    __shared__ float s_ps[NT * DP];
    int tid = threadIdx.x;
    for (int i = tid; i < NT * DC; i += 256) {
        float v = cs[i];
        s_cs[i] = (v > 0.f) ? 1.f : ((v < 0.f) ? -1.f : 0.f);
    }
    for (int i = tid; i < NT * DP; i += 256) {
        float v = ps[i];
        s_ps[i] = (v > 0.f) ? 1.f : ((v < 0.f) ? -1.f : 0.f);
    }
    __syncthreads();

    int token = blockIdx.x * 8 + (tid >> 5);
    int lane  = tid & 31;
    const float* xr  = x  + (size_t)token * DC;
    const float* per = pe + (size_t)(token % SEQ) * DP;

    float ac[NT], ap[NT];
#pragma unroll
    for (int t = 0; t < NT; t++) { ac[t] = 0.f; ap[t] = 0.f; }

    for (int d = lane; d < DC; d += 32) {
        float xv = xr[d];
#pragma unroll
        for (int t = 0; t < NT; t++) ac[t] += s_cs[t * DC + d] * xv;
    }
#pragma unroll
    for (int d = lane; d < DP; d += 32) {
        float pv = per[d];
#pragma unroll
        for (int t = 0; t < NT; t++) ap[t] += s_ps[t * DP + d] * pv;
    }
#pragma unroll
    for (int t = 0; t < NT; t++) {
        float v = ac[t];
#pragma unroll
        for (int o = 16; o; o >>= 1) v += __shfl_xor_sync(0xffffffffu, v, o);
        ac[t] = v;
        float w = ap[t];
#pragma unroll
        for (int o = 16; o; o >>= 1) w += __shfl_xor_sync(0xffffffffu, w, o);
        ap[t] = w;
    }
    if (lane == 0) {
        float pw = 1.f / (1.f + expf(-pwp[0]));
        float cw = 1.f / (1.f + expf(-cwp[0]));
        float tot = pw + cw;
        pw /= tot; cw /= tot;
        float best = -3.0e38f;
        int bi = 0;
#pragma unroll
        for (int t = 0; t < NT; t++) {
            float sc = pw * ap[t] + cw * ac[t];
            if (sc > best) { best = sc; bi = t; }   // first-max, matches argmax
        }
        g_tile_of[token] = bi;
        atomicAdd(&g_counts[bi], 1);
    }
}

__global__ void k_scan() {
    int acc = 0;
    for (int t = 0; t < NT; t++) {
        g_offsets[t] = acc;
        acc += g_counts[t];
        g_cursor[t] = 0;
    }
}

__global__ void k_build() {
    int token = blockIdx.x * 256 + threadIdx.x;
    if (token < NTOK) {
        int t = g_tile_of[token];
        int p = atomicAdd(&g_cursor[t], 1);
        g_perm[g_offsets[t] + p] = token;
    }
}

// ---------------- grouped GEMM (tf32 mma.sync m16n8k8) ----------------
// FIRST=true : C = gelu( gather(x, perm) @ W1[t] + b1[t] ) -> g_h   (K=1024, N=4096)
// FIRST=false: out[perm] = g_h @ W2[t] + b2[t]                      (K=4096, N=1024)
template <int KD, int ND, bool FIRST>
__global__ void __launch_bounds__(256) k_gemm(const float* __restrict__ Xin,
                                              const float* __restrict__ W,
                                              const float* __restrict__ Bias,
                                              float* __restrict__ Out) {
    __shared__ uint32_t As[BM][BK + 4];  // tf32 bits, conflict-free frag reads
    __shared__ uint32_t Bs[BK][BN + 8];

    // map blockIdx.y -> (tile, local m-block)
    int mb = blockIdx.y;
    int tile = -1, mloc = 0, accb = 0;
#pragma unroll
    for (int t = 0; t < NT; t++) {
        int nb = (g_counts[t] + BM - 1) >> 7;
        if (tile < 0 && mb < accb + nb) { tile = t; mloc = mb - accb; }
        accb += nb;
    }
    if (tile < 0) return;

    int cnt   = g_counts[tile];
    int off   = g_offsets[tile];
    int n0    = blockIdx.x * BN;
    int mbase = mloc * BM;
    const float* Wt = W + (size_t)tile * KD * ND;

    int tid = threadIdx.x, lane = tid & 31, wid = tid >> 5;
    int warp_m = wid & 3, warp_n = wid >> 2;      // 4x2 warps of 32x32 tiles
    int g = lane >> 2, tg = lane & 3;

    // fixed A-row pointers for this thread's 4 float4 loads per K-step
    const float* arow[4];
#pragma unroll
    for (int i = 0; i < 4; i++) {
        int f4 = tid + i * 256;
        int r  = f4 >> 3;
        bool valid = (mbase + r) < cnt;
        if (FIRST)
            arow[i] = valid ? (Xin + (size_t)g_perm[off + mbase + r] * KD) : nullptr;
        else
            arow[i] = valid ? (g_h + (size_t)(off + mbase + r) * KD) : nullptr;
    }

    float accum[2][4][4];
#pragma unroll
    for (int mt = 0; mt < 2; mt++)
#pragma unroll
        for (int nt = 0; nt < 4; nt++)
#pragma unroll
            for (int j = 0; j < 4; j++) accum[mt][nt][j] = 0.f;

    for (int k0 = 0; k0 < KD; k0 += BK) {
#pragma unroll
        for (int i = 0; i < 4; i++) {
            int f4 = tid + i * 256;
            int r  = f4 >> 3;
            int c  = (f4 & 7) * 4;
            float4 v = make_float4(0.f, 0.f, 0.f, 0.f);
            if (arow[i]) v = *(const float4*)(arow[i] + k0 + c);
            As[r][c + 0] = f2tf32(v.x);
            As[r][c + 1] = f2tf32(v.y);
            As[r][c + 2] = f2tf32(v.z);
            As[r][c + 3] = f2tf32(v.w);
        }
#pragma unroll
        for (int i = 0; i < 2; i++) {
            int f4 = tid + i * 256;
            int r  = f4 >> 4;
            int c  = (f4 & 15) * 4;
            float4 v = *(const float4*)(Wt + (size_t)(k0 + r) * ND + n0 + c);
            Bs[r][c + 0] = f2tf32(v.x);
            Bs[r][c + 1] = f2tf32(v.y);
            Bs[r][c + 2] = f2tf32(v.z);
            Bs[r][c + 3] = f2tf32(v.w);
        }
        __syncthreads();

#pragma unroll
        for (int ks = 0; ks < BK / 8; ks++) {
            int kk = ks * 8;
            uint32_t af[2][4], bf[4][2];
#pragma unroll
            for (int mt = 0; mt < 2; mt++) {
                int r = warp_m * 32 + mt * 16 + g;
                af[mt][0] = As[r][kk + tg];
                af[mt][1] = As[r + 8][kk + tg];
                af[mt][2] = As[r][kk + tg + 4];
                af[mt][3] = As[r + 8][kk + tg + 4];
            }
#pragma unroll
            for (int nt = 0; nt < 4; nt++) {
                int c = warp_n * 32 + nt * 8 + g;
                bf[nt][0] = Bs[kk + tg][c];
                bf[nt][1] = Bs[kk + tg + 4][c];
            }
#pragma unroll
            for (int mt = 0; mt < 2; mt++)
#pragma unroll
                for (int nt = 0; nt < 4; nt++)
                    mma8(accum[mt][nt], af[mt], bf[nt]);
        }
        __syncthreads();
    }

    // epilogue
#pragma unroll
    for (int mt = 0; mt < 2; mt++) {
#pragma unroll
        for (int nt = 0; nt < 4; nt++) {
            int col = n0 + warp_n * 32 + nt * 8 + tg * 2;
            float b0 = Bias[tile * ND + col];
            float b1v = Bias[tile * ND + col + 1];
            int rl = mbase + warp_m * 32 + mt * 16 + g;
#pragma unroll
            for (int h = 0; h < 2; h++) {
                int rr = rl + h * 8;
                if (rr < cnt) {
                    float v0 = accum[mt][nt][h * 2 + 0] + b0;
                    float v1 = accum[mt][nt][h * 2 + 1] + b1v;
                    if (FIRST) {
                        v0 = 0.5f * v0 * (1.f + erff(v0 * 0.70710678118654752f));
                        v1 = 0.5f * v1 * (1.f + erff(v1 * 0.70710678118654752f));
                        *(float2*)&g_h[(size_t)(off + rr) * ND + col] = make_float2(v0, v1);
                    } else {
                        *(float2*)&Out[(size_t)g_perm[off + rr] * ND + col] = make_float2(v0, v1);
                    }
                }
            }
        }
    }
}

extern "C" void kernel_launch(void* const* d_in, const int* in_sizes, int n_in,
                              void* d_out, int out_size) {
    const float* x  = (const float*)d_in[0];
    const float* pe = (const float*)d_in[1];
    const float* pw = (const float*)d_in[2];
    const float* cw = (const float*)d_in[3];
    const float* ps = (const float*)d_in[4];
    const float* cs = (const float*)d_in[5];
    const float* W1 = (const float*)d_in[6];
    const float* b1 = (const float*)d_in[7];
    const float* W2 = (const float*)d_in[8];
    const float* b2 = (const float*)d_in[9];
    float* out = (float*)d_out;

    k_init<<<1, NT>>>();
    k_route<<<NTOK / 8, 256>>>(x, pe, pw, cw, ps, cs);
    k_scan<<<1, 1>>>();
    k_build<<<NTOK / 256, 256>>>();

    dim3 g1(DH / BN, MAXMB);
    k_gemm<DC, DH, true><<<g1, 256>>>(x, W1, b1, nullptr);
    dim3 g2(DC / BN, MAXMB);
    k_gemm<DH, DC, false><<<g2, 256>>>(nullptr, W2, b2, out);
}

// round 4
// speedup vs baseline: 1.4314x; 1.4314x over previous
#include <cuda_runtime.h>
#include <cstdint>
#include <math.h>

#define BATCH 16
#define SEQ   512
#define DC    1024
#define DP    64
#define NT    8
#define DH    4096
#define NTOK  (BATCH*SEQ)

// ---- GEMM tiling: CTA 128(tokens) x 256(wcols) x 32(k), 8 warps of 64x64 ----
#define BM 128
#define BN 256
#define BK 32
#define A_STRIDE 36                        // floats per padded A row (144B)
#define B_STRIDE 264                       // floats per padded B row (1056B)
#define A_BYTES  (BM*A_STRIDE*4)           // 18432
#define STAGEB   (A_BYTES + BK*B_STRIDE*4) // 52224
#define NSTAGE   3
#define SMEMSZ   (NSTAGE*STAGEB)           // 156672
#define MAXTB    72                        // sum ceil(cnt/128) <= 64+8

// ---- scratch (static __device__: allocation-free) ----
__device__ int   g_tile_of[NTOK];
__device__ int   g_counts[NT];
__device__ int   g_offsets[NT];
__device__ int   g_cursor[NT];
__device__ int   g_perm[NTOK];
__device__ float g_xr[(size_t)NTOK * DC];  // tf32-rounded x
__device__ float g_h[(size_t)NTOK * DH];   // intermediate (permuted, tf32-rounded)

// ================= helpers =================
__device__ __forceinline__ uint32_t smem_u32(const void* p) {
    uint32_t a;
    asm("{ .reg .u64 t; cvta.to.shared.u64 t, %1; cvt.u32.u64 %0, t; }" : "=r"(a) : "l"(p));
    return a;
}
__device__ __forceinline__ uint32_t f2tf32(float f) {
    uint32_t r;
    asm("cvt.rna.tf32.f32 %0, %1;" : "=r"(r) : "f"(f));
    return r;
}
__device__ __forceinline__ void cp_async16(uint32_t dst, const void* src) {
    asm volatile("cp.async.cg.shared.global [%0], [%1], 16;" :: "r"(dst), "l"(src));
}
__device__ __forceinline__ void cp_commit() { asm volatile("cp.async.commit_group;" ::: "memory"); }
__device__ __forceinline__ void cp_wait1()  { asm volatile("cp.async.wait_group 1;" ::: "memory"); }

__device__ __forceinline__ void ldsm4(uint32_t* r, uint32_t addr) {
    asm volatile("ldmatrix.sync.aligned.m8n8.x4.shared.b16 {%0,%1,%2,%3}, [%4];"
                 : "=r"(r[0]), "=r"(r[1]), "=r"(r[2]), "=r"(r[3]) : "r"(addr));
}
__device__ __forceinline__ void mma8(float* c, const uint32_t* a, const uint32_t* b) {
    asm volatile(
        "mma.sync.aligned.m16n8k8.row.col.f32.tf32.tf32.f32 "
        "{%0,%1,%2,%3}, {%4,%5,%6,%7}, {%8,%9}, {%0,%1,%2,%3};\n"
        : "+f"(c[0]), "+f"(c[1]), "+f"(c[2]), "+f"(c[3])
        : "r"(a[0]), "r"(a[1]), "r"(a[2]), "r"(a[3]), "r"(b[0]), "r"(b[1]));
}

// ================= routing =================
__global__ void k_init() { if (threadIdx.x < NT) g_counts[threadIdx.x] = 0; }

__global__ void k_route(const float* __restrict__ x, const float* __restrict__ pe,
                        const float* __restrict__ pwp, const float* __restrict__ cwp,
                        const float* __restrict__ ps, const float* __restrict__ cs) {
    __shared__ float s_cs[NT * DC];
    __shared__ float s_ps[NT * DP];
    int tid = threadIdx.x;
    for (int i = tid; i < NT * DC; i += 256) {
        float v = cs[i];
        s_cs[i] = (v > 0.f) ? 1.f : ((v < 0.f) ? -1.f : 0.f);
    }
    for (int i = tid; i < NT * DP; i += 256) {
        float v = ps[i];
        s_ps[i] = (v > 0.f) ? 1.f : ((v < 0.f) ? -1.f : 0.f);
    }
    __syncthreads();

    int token = blockIdx.x * 8 + (tid >> 5);
    int lane  = tid & 31;
    const float* xr  = x  + (size_t)token * DC;
    const float* per = pe + (size_t)(token % SEQ) * DP;

    float ac[NT], ap[NT];
#pragma unroll
    for (int t = 0; t < NT; t++) { ac[t] = 0.f; ap[t] = 0.f; }
    for (int d = lane; d < DC; d += 32) {
        float xv = xr[d];
        g_xr[(size_t)token * DC + d] = __uint_as_float(f2tf32(xv));  // pre-rounded GEMM1 A
#pragma unroll
        for (int t = 0; t < NT; t++) ac[t] += s_cs[t * DC + d] * xv;
    }
#pragma unroll
    for (int d = lane; d < DP; d += 32) {
        float pv = per[d];
#pragma unroll
        for (int t = 0; t < NT; t++) ap[t] += s_ps[t * DP + d] * pv;
    }
#pragma unroll
    for (int t = 0; t < NT; t++) {
        float v = ac[t];
#pragma unroll
        for (int o = 16; o; o >>= 1) v += __shfl_xor_sync(0xffffffffu, v, o);
        ac[t] = v;
        float w = ap[t];
#pragma unroll
        for (int o = 16; o; o >>= 1) w += __shfl_xor_sync(0xffffffffu, w, o);
        ap[t] = w;
    }
    if (lane == 0) {
        float pw = 1.f / (1.f + expf(-pwp[0]));
        float cw = 1.f / (1.f + expf(-cwp[0]));
        float tot = pw + cw;
        pw /= tot; cw /= tot;
        float best = -3.0e38f;
        int bi = 0;
#pragma unroll
        for (int t = 0; t < NT; t++) {
            float sc = pw * ap[t] + cw * ac[t];
            if (sc > best) { best = sc; bi = t; }
        }
        g_tile_of[token] = bi;
        atomicAdd(&g_counts[bi], 1);
    }
}

__global__ void k_scan() {
    int acc = 0;
    for (int t = 0; t < NT; t++) {
        g_offsets[t] = acc;
        acc += g_counts[t];
        g_cursor[t] = 0;
    }
}

__global__ void k_build() {
    int token = blockIdx.x * 256 + threadIdx.x;
    if (token < NTOK) {
        int t = g_tile_of[token];
        int p = atomicAdd(&g_cursor[t], 1);
        g_perm[g_offsets[t] + p] = token;
    }
}

// ================= grouped GEMM: mma.sync tf32, cp.async 3-stage, ldmatrix A =================
// A = token rows (gathered; pre-rounded to tf32), B = weights W[t] ([K][N], N contiguous, raw).
// FIRST: g_h = tf32(gelu(A@W1 + b1)); else: out[perm] = g_h@W2 + b2.
template <int KD, int ND, bool FIRST>
__global__ void __launch_bounds__(256, 1)
k_gemm(const float* __restrict__ Aglob, const float* __restrict__ W,
       const float* __restrict__ Bias, float* __restrict__ Out)
{
    extern __shared__ char dsm[];
    uint32_t sb = smem_u32(dsm);

    int tid = threadIdx.x, lane = tid & 31, wid = tid >> 5;
    int warp_m = wid & 1, warp_n = wid >> 1;          // 2 x 4 warps of 64x64
    int g = lane >> 2, tg = lane & 3;

    // ---- map blockIdx.y -> (tile, local token-block) ----
    int tb = blockIdx.y;
    int tile = -1, tloc = 0, acc = 0;
#pragma unroll
    for (int t = 0; t < NT; t++) {
        int nb = (g_counts[t] + BM - 1) >> 7;
        if (tile < 0 && tb < acc + nb) { tile = t; tloc = tb - acc; }
        acc += nb;
    }
    if (tile < 0) return;
    int cnt  = g_counts[tile];
    int off  = g_offsets[tile];
    int tok0 = tloc * BM;
    int n0   = blockIdx.x * BN;
    const float* Wt = W + (size_t)tile * KD * ND;

    // ---- per-thread load geometry ----
    const float* aptr[4];
    uint32_t a_dst[4];
#pragma unroll
    for (int q = 0; q < 4; q++) {
        int r  = (tid >> 3) + 32 * q;
        int tk = tok0 + r; if (tk >= cnt) tk = cnt - 1;    // clamp; garbage rows discarded
        aptr[q] = FIRST ? (Aglob + (size_t)g_perm[off + tk] * KD)
                        : (g_h + (size_t)(off + tk) * KD);
        a_dst[q] = (uint32_t)(r * (A_STRIDE * 4) + (tid & 7) * 16);
    }
    int a_col = (tid & 7) * 4;
    uint32_t b_dst0 = (uint32_t)(A_BYTES + (tid >> 6) * (B_STRIDE * 4) + (tid & 63) * 16);
    const float* b_src0 = Wt + (size_t)(tid >> 6) * ND + n0 + (tid & 63) * 4;

    auto pf = [&](int j, int s) {
        uint32_t st = sb + (uint32_t)s * STAGEB;
        int k0 = j * BK;
#pragma unroll
        for (int q = 0; q < 4; q++)
            cp_async16(st + a_dst[q], aptr[q] + k0 + a_col);
        const float* bs = b_src0 + (size_t)k0 * ND;
#pragma unroll
        for (int q = 0; q < 8; q++)
            cp_async16(st + b_dst0 + (uint32_t)q * (4 * B_STRIDE * 4), bs + (size_t)q * 4 * ND);
    };

    // ---- fragment geometry ----
    uint32_t a_frag_off = (uint32_t)((warp_m * 64 + (lane & 7) + ((lane >> 3) & 1) * 8) * (A_STRIDE * 4)
                                     + (lane >> 4) * 16);
    int cb = warp_n * 64 + g;

    float accf[4][8][4];
#pragma unroll
    for (int mt = 0; mt < 4; mt++)
#pragma unroll
        for (int nt = 0; nt < 8; nt++)
#pragma unroll
            for (int j = 0; j < 4; j++) accf[mt][nt][j] = 0.f;

    constexpr int NCH = KD / BK;

    pf(0, 0); cp_commit();
    pf(1, 1); cp_commit();

    int s = 0;
    for (int i = 0; i < NCH; i++) {
        cp_wait1();                 // chunk i resident (only chunk i+1 may be pending)
        __syncthreads();            // cp.async visible to all; stage (i+2)%3 free of readers

        if (i + 2 < NCH) pf(i + 2, (i + 2) % NSTAGE);
        cp_commit();                // always commit to keep group accounting exact

        uint32_t abase = sb + (uint32_t)s * STAGEB + a_frag_off;
        const uint32_t* Bsw = (const uint32_t*)(dsm + (size_t)s * STAGEB + A_BYTES);
#pragma unroll
        for (int ks = 0; ks < 4; ks++) {
            uint32_t af[4][4];
#pragma unroll
            for (int mt = 0; mt < 4; mt++)
                ldsm4(af[mt], abase + (uint32_t)(mt * 16 * A_STRIDE * 4 + ks * 32));
            uint32_t bf[8][2];
            int rb = (ks * 8 + tg) * B_STRIDE;
#pragma unroll
            for (int nt = 0; nt < 8; nt++) {
                int c = cb + nt * 8;
                bf[nt][0] = Bsw[rb + c];
                bf[nt][1] = Bsw[rb + 4 * B_STRIDE + c];
            }
#pragma unroll
            for (int mt = 0; mt < 4; mt++)
#pragma unroll
                for (int nt = 0; nt < 8; nt++)
                    mma8(accf[mt][nt], af[mt], bf[nt]);
        }
        s++; if (s == NSTAGE) s = 0;
    }

    // ---- epilogue ----
#pragma unroll
    for (int nt = 0; nt < 8; nt++) {
        int col = n0 + warp_n * 64 + nt * 8 + tg * 2;
        float2 bv = *(const float2*)&Bias[(size_t)tile * ND + col];
#pragma unroll
        for (int mt = 0; mt < 4; mt++) {
            int rbase = tok0 + warp_m * 64 + mt * 16 + g;
#pragma unroll
            for (int h = 0; h < 2; h++) {
                int row = rbase + h * 8;
                if (row < cnt) {
                    float v0 = accf[mt][nt][h * 2 + 0] + bv.x;
                    float v1 = accf[mt][nt][h * 2 + 1] + bv.y;
                    if (FIRST) {
                        v0 = 0.5f * v0 * (1.f + erff(v0 * 0.70710678118654752f));
                        v1 = 0.5f * v1 * (1.f + erff(v1 * 0.70710678118654752f));
                        float2 o = make_float2(__uint_as_float(f2tf32(v0)),
                                               __uint_as_float(f2tf32(v1)));
                        *(float2*)&g_h[(size_t)(off + row) * ND + col] = o;
                    } else {
                        float2 o = make_float2(v0, v1);
                        *(float2*)&Out[(size_t)g_perm[off + row] * ND + col] = o;
                    }
                }
            }
        }
    }
}

extern "C" void kernel_launch(void* const* d_in, const int* in_sizes, int n_in,
                              void* d_out, int out_size) {
    const float* x  = (const float*)d_in[0];
    const float* pe = (const float*)d_in[1];
    const float* pw = (const float*)d_in[2];
    const float* cw = (const float*)d_in[3];
    const float* ps = (const float*)d_in[4];
    const float* cs = (const float*)d_in[5];
    const float* W1 = (const float*)d_in[6];
    const float* b1 = (const float*)d_in[7];
    const float* W2 = (const float*)d_in[8];
    const float* b2 = (const float*)d_in[9];
    float* out = (float*)d_out;

    static float* xr_addr = nullptr;
    if (!xr_addr) cudaGetSymbolAddress((void**)&xr_addr, g_xr);  // address query, no alloc

    cudaFuncSetAttribute(k_gemm<DC, DH, true>,  cudaFuncAttributeMaxDynamicSharedMemorySize, SMEMSZ);
    cudaFuncSetAttribute(k_gemm<DH, DC, false>, cudaFuncAttributeMaxDynamicSharedMemorySize, SMEMSZ);

    k_init<<<1, NT>>>();
    k_route<<<NTOK / 8, 256>>>(x, pe, pw, cw, ps, cs);
    k_scan<<<1, 1>>>();
    k_build<<<NTOK / 256, 256>>>();

    k_gemm<DC, DH, true><<<dim3(DH / BN, MAXTB), 256, SMEMSZ>>>(xr_addr, W1, b1, nullptr);
    k_gemm<DH, DC, false><<<dim3(DC / BN, MAXTB), 256, SMEMSZ>>>(nullptr, W2, b2, out);
}

// round 5
// speedup vs baseline: 2.2167x; 1.5487x over previous
#include <cuda_runtime.h>
#include <cuda_fp16.h>
#include <cstdint>
#include <math.h>

#define BATCH 16
#define SEQ   512
#define DC    1024
#define DP    64
#define NT    8
#define DH    4096
#define NTOK  (BATCH*SEQ)

// ---- GEMM tiling: CTA 128(tokens) x 128(wcols) x 32(k), 4 warps of 64x64, fp16 m16n8k16 ----
#define BM 128
#define BN 128
#define BK 32
#define ASTRB 80                    // bytes per A row (64 data + 16 pad)
#define BSTRB 272                   // bytes per B row (256 data + 16 pad)
#define B_OFF (BM*ASTRB)            // 10240
#define STAGEB (B_OFF + BK*BSTRB)   // 18944
#define NSTAGE 4
#define SMEMSZ (NSTAGE*STAGEB)      // 75776
#define MAXTB  72

// ---- scratch (static __device__: allocation-free) ----
__device__ int    g_tile_of[NTOK];
__device__ int    g_counts[NT];
__device__ int    g_offsets[NT];
__device__ int    g_cursor[NT];
__device__ int    g_perm[NTOK];
__device__ __half g_xh[(size_t)NTOK * DC];       // x rounded to half
__device__ __half g_h[(size_t)NTOK * DH];        // intermediate (permuted), half
__device__ __half g_w1h[(size_t)NT * DC * DH];   // W1 in half
__device__ __half g_w2h[(size_t)NT * DH * DC];   // W2 in half

// ================= helpers =================
__device__ __forceinline__ uint32_t smem_u32(const void* p) {
    uint32_t a;
    asm("{ .reg .u64 t; cvta.to.shared.u64 t, %1; cvt.u32.u64 %0, t; }" : "=r"(a) : "l"(p));
    return a;
}
__device__ __forceinline__ void cp_async16(uint32_t dst, const void* src) {
    asm volatile("cp.async.cg.shared.global [%0], [%1], 16;" :: "r"(dst), "l"(src));
}
__device__ __forceinline__ void cp_commit() { asm volatile("cp.async.commit_group;" ::: "memory"); }
__device__ __forceinline__ void cp_wait2()  { asm volatile("cp.async.wait_group 2;" ::: "memory"); }

__device__ __forceinline__ void ldsm4(uint32_t* r, uint32_t addr) {
    asm volatile("ldmatrix.sync.aligned.m8n8.x4.shared.b16 {%0,%1,%2,%3}, [%4];"
                 : "=r"(r[0]), "=r"(r[1]), "=r"(r[2]), "=r"(r[3]) : "r"(addr));
}
__device__ __forceinline__ void ldsm4t(uint32_t* r, uint32_t addr) {
    asm volatile("ldmatrix.sync.aligned.m8n8.x4.trans.shared.b16 {%0,%1,%2,%3}, [%4];"
                 : "=r"(r[0]), "=r"(r[1]), "=r"(r[2]), "=r"(r[3]) : "r"(addr));
}
__device__ __forceinline__ void mma16(float* c, const uint32_t* a, const uint32_t* b) {
    asm volatile(
        "mma.sync.aligned.m16n8k16.row.col.f32.f16.f16.f32 "
        "{%0,%1,%2,%3}, {%4,%5,%6,%7}, {%8,%9}, {%0,%1,%2,%3};\n"
        : "+f"(c[0]), "+f"(c[1]), "+f"(c[2]), "+f"(c[3])
        : "r"(a[0]), "r"(a[1]), "r"(a[2]), "r"(a[3]), "r"(b[0]), "r"(b[1]));
}

// ================= weight conversion (fp32 -> fp16, RN) =================
__global__ void k_conv(const float* __restrict__ src, __half* __restrict__ dst) {
    size_t i = (size_t)blockIdx.x * 256 + threadIdx.x;   // one 16B output granule
    const float4* s = (const float4*)src + i * 2;
    float4 v0 = s[0], v1 = s[1];
    __half2 h0 = __floats2half2_rn(v0.x, v0.y);
    __half2 h1 = __floats2half2_rn(v0.z, v0.w);
    __half2 h2 = __floats2half2_rn(v1.x, v1.y);
    __half2 h3 = __floats2half2_rn(v1.z, v1.w);
    uint4 o;
    o.x = *(uint32_t*)&h0; o.y = *(uint32_t*)&h1;
    o.z = *(uint32_t*)&h2; o.w = *(uint32_t*)&h3;
    ((uint4*)dst)[i] = o;
}

// ================= routing =================
__global__ void k_init() { if (threadIdx.x < NT) g_counts[threadIdx.x] = 0; }

__global__ void k_route(const float* __restrict__ x, const float* __restrict__ pe,
                        const float* __restrict__ pwp, const float* __restrict__ cwp,
                        const float* __restrict__ ps, const float* __restrict__ cs) {
    __shared__ float s_cs[NT * DC];
    __shared__ float s_ps[NT * DP];
    int tid = threadIdx.x;
    for (int i = tid; i < NT * DC; i += 256) {
        float v = cs[i];
        s_cs[i] = (v > 0.f) ? 1.f : ((v < 0.f) ? -1.f : 0.f);
    }
    for (int i = tid; i < NT * DP; i += 256) {
        float v = ps[i];
        s_ps[i] = (v > 0.f) ? 1.f : ((v < 0.f) ? -1.f : 0.f);
    }
    __syncthreads();

    int token = blockIdx.x * 8 + (tid >> 5);
    int lane  = tid & 31;
    const float* xr  = x  + (size_t)token * DC;
    const float* per = pe + (size_t)(token % SEQ) * DP;

    float ac[NT], ap[NT];
#pragma unroll
    for (int t = 0; t < NT; t++) { ac[t] = 0.f; ap[t] = 0.f; }
    for (int d = lane; d < DC; d += 32) {
        float xv = xr[d];
        g_xh[(size_t)token * DC + d] = __float2half_rn(xv);   // pre-rounded GEMM1 A
#pragma unroll
        for (int t = 0; t < NT; t++) ac[t] += s_cs[t * DC + d] * xv;
    }
#pragma unroll
    for (int d = lane; d < DP; d += 32) {
        float pv = per[d];
#pragma unroll
        for (int t = 0; t < NT; t++) ap[t] += s_ps[t * DP + d] * pv;
    }
#pragma unroll
    for (int t = 0; t < NT; t++) {
        float v = ac[t];
#pragma unroll
        for (int o = 16; o; o >>= 1) v += __shfl_xor_sync(0xffffffffu, v, o);
        ac[t] = v;
        float w = ap[t];
#pragma unroll
        for (int o = 16; o; o >>= 1) w += __shfl_xor_sync(0xffffffffu, w, o);
        ap[t] = w;
    }
    if (lane == 0) {
        float pw = 1.f / (1.f + expf(-pwp[0]));
        float cw = 1.f / (1.f + expf(-cwp[0]));
        float tot = pw + cw;
        pw /= tot; cw /= tot;
        float best = -3.0e38f;
        int bi = 0;
#pragma unroll
        for (int t = 0; t < NT; t++) {
            float sc = pw * ap[t] + cw * ac[t];
            if (sc > best) { best = sc; bi = t; }
        }
        g_tile_of[token] = bi;
        atomicAdd(&g_counts[bi], 1);
    }
}

__global__ void k_scan() {
    int acc = 0;
    for (int t = 0; t < NT; t++) {
        g_offsets[t] = acc;
        acc += g_counts[t];
        g_cursor[t] = 0;
    }
}

__global__ void k_build() {
    int token = blockIdx.x * 256 + threadIdx.x;
    if (token < NTOK) {
        int t = g_tile_of[token];
        int p = atomicAdd(&g_cursor[t], 1);
        g_perm[g_offsets[t] + p] = token;
    }
}

// ================= grouped GEMM: fp16 m16n8k16, cp.async 4-stage, ldmatrix A+B =================
// FIRST: g_h = half(gelu(gather(g_xh)@W1h + b1)); else: out[perm] = g_h@W2h + b2.
template <int KD, int ND, bool FIRST>
__global__ void __launch_bounds__(128, 2)
k_gemm(const __half* __restrict__ Wh, const float* __restrict__ Bias, float* __restrict__ Out)
{
    extern __shared__ char dsm[];
    uint32_t sb = smem_u32(dsm);

    int tid = threadIdx.x, lane = tid & 31, wid = tid >> 5;
    int warp_m = wid & 1, warp_n = wid >> 1;          // 2 x 2 warps of 64x64
    int g = lane >> 2, tg = lane & 3;

    // ---- map blockIdx.y -> (tile, local token-block) ----
    int tb = blockIdx.y;
    int tile = -1, tloc = 0, acc = 0;
#pragma unroll
    for (int t = 0; t < NT; t++) {
        int nb = (g_counts[t] + BM - 1) >> 7;
        if (tile < 0 && tb < acc + nb) { tile = t; tloc = tb - acc; }
        acc += nb;
    }
    if (tile < 0) return;
    int cnt  = g_counts[tile];
    int off  = g_offsets[tile];
    int tok0 = tloc * BM;
    int n0   = blockIdx.x * BN;
    const __half* Wt = Wh + (size_t)tile * KD * ND;

    // ---- per-thread cp.async geometry ----
    // A: 4 granules; granule q: row = (tid>>2)+32q, seg = tid&3 (16B within 64B row)
    const __half* aptr[4];
    uint32_t a_dst[4];
#pragma unroll
    for (int q = 0; q < 4; q++) {
        int r  = (tid >> 2) + 32 * q;
        int tk = tok0 + r; if (tk >= cnt) tk = cnt - 1;   // clamp; garbage rows masked later
        const __half* base = FIRST ? (g_xh + (size_t)g_perm[off + tk] * KD)
                                   : (g_h + (size_t)(off + tk) * KD);
        aptr[q] = base + (tid & 3) * 8;
        a_dst[q] = (uint32_t)(r * ASTRB + (tid & 3) * 16);
    }
    // B: 4 granules; granule q: row = (tid>>4)+8q, seg = tid&15 (16B within 256B row)
    const __half* bptr[4];
    uint32_t b_dst[4];
#pragma unroll
    for (int q = 0; q < 4; q++) {
        int r = (tid >> 4) + 8 * q;
        bptr[q] = Wt + (size_t)r * ND + n0 + (tid & 15) * 8;
        b_dst[q] = (uint32_t)(B_OFF + r * BSTRB + (tid & 15) * 16);
    }

    auto pf = [&](int j, int s) {
        uint32_t st = sb + (uint32_t)s * STAGEB;
        int k0 = j * BK;
#pragma unroll
        for (int q = 0; q < 4; q++) cp_async16(st + a_dst[q], aptr[q] + k0);
#pragma unroll
        for (int q = 0; q < 4; q++) cp_async16(st + b_dst[q], bptr[q] + (size_t)k0 * ND);
    };

    // ---- fragment geometry ----
    // A ldsm.x4: lane row = lane&15 (+ warp_m*64 + mt*16), k-16B-half = lane>>4, +ks*32B
    uint32_t a_frag = (uint32_t)((warp_m * 64 + (lane & 15)) * ASTRB + (lane >> 4) * 16);
    // B ldsm.x4.trans: lane k-row = (lane&7)+((lane>>3)&1)*8 (+ks*16), n-off = warp_n*64+(lane>>4)*8 (+nt*16)
    uint32_t b_frag = (uint32_t)(B_OFF + ((lane & 7) + ((lane >> 3) & 1) * 8) * BSTRB
                                 + (warp_n * 64 + (lane >> 4) * 8) * 2);

    float accf[4][8][4];
#pragma unroll
    for (int mt = 0; mt < 4; mt++)
#pragma unroll
        for (int j = 0; j < 8; j++)
#pragma unroll
            for (int e = 0; e < 4; e++) accf[mt][j][e] = 0.f;

    constexpr int NCH = KD / BK;

    pf(0, 0); cp_commit();
    pf(1, 1); cp_commit();
    pf(2, 2); cp_commit();

    int s = 0;
    for (int i = 0; i < NCH; i++) {
        cp_wait2();                 // chunk i resident (i+1, i+2 may pend)
        __syncthreads();            // data visible; stage (i+3)%4 free of readers

        if (i + 3 < NCH) pf(i + 3, (i + 3) & 3);
        cp_commit();                // commit every iter: exact group accounting

        uint32_t stg = sb + (uint32_t)s * STAGEB;
#pragma unroll
        for (int ks = 0; ks < 2; ks++) {
            uint32_t af[4][4], bf[4][4];
#pragma unroll
            for (int mt = 0; mt < 4; mt++)
                ldsm4(af[mt], stg + a_frag + (uint32_t)(mt * 16 * ASTRB + ks * 32));
#pragma unroll
            for (int nt = 0; nt < 4; nt++)
                ldsm4t(bf[nt], stg + b_frag + (uint32_t)(ks * 16 * BSTRB + nt * 32));
#pragma unroll
            for (int mt = 0; mt < 4; mt++)
#pragma unroll
                for (int nt = 0; nt < 4; nt++) {
                    mma16(accf[mt][nt * 2 + 0], af[mt], &bf[nt][0]);
                    mma16(accf[mt][nt * 2 + 1], af[mt], &bf[nt][2]);
                }
        }
        s = (s + 1) & 3;
    }

    // ---- epilogue ----
#pragma unroll
    for (int j = 0; j < 8; j++) {
        int col = n0 + warp_n * 64 + j * 8 + tg * 2;
        float2 bv = *(const float2*)&Bias[(size_t)tile * ND + col];
#pragma unroll
        for (int mt = 0; mt < 4; mt++) {
            int rbase = tok0 + warp_m * 64 + mt * 16 + g;
#pragma unroll
            for (int h = 0; h < 2; h++) {
                int row = rbase + h * 8;
                if (row < cnt) {
                    float v0 = accf[mt][j][h * 2 + 0] + bv.x;
                    float v1 = accf[mt][j][h * 2 + 1] + bv.y;
                    if (FIRST) {
                        v0 = 0.5f * v0 * (1.f + erff(v0 * 0.70710678118654752f));
                        v1 = 0.5f * v1 * (1.f + erff(v1 * 0.70710678118654752f));
                        __half2 hv = __floats2half2_rn(v0, v1);
                        *(__half2*)&g_h[(size_t)(off + row) * ND + col] = hv;
                    } else {
                        *(float2*)&Out[(size_t)g_perm[off + row] * ND + col] = make_float2(v0, v1);
                    }
                }
            }
        }
    }
}

extern "C" void kernel_launch(void* const* d_in, const int* in_sizes, int n_in,
                              void* d_out, int out_size) {
    const float* x  = (const float*)d_in[0];
    const float* pe = (const float*)d_in[1];
    const float* pw = (const float*)d_in[2];
    const float* cw = (const float*)d_in[3];
    const float* ps = (const float*)d_in[4];
    const float* cs = (const float*)d_in[5];
    const float* W1 = (const float*)d_in[6];
    const float* b1 = (const float*)d_in[7];
    const float* W2 = (const float*)d_in[8];
    const float* b2 = (const float*)d_in[9];
    float* out = (float*)d_out;

    __half *w1h, *w2h;
    cudaGetSymbolAddress((void**)&w1h, g_w1h);   // address queries only, no alloc
    cudaGetSymbolAddress((void**)&w2h, g_w2h);

    cudaFuncSetAttribute(k_gemm<DC, DH, true>,  cudaFuncAttributeMaxDynamicSharedMemorySize, SMEMSZ);
    cudaFuncSetAttribute(k_gemm<DH, DC, false>, cudaFuncAttributeMaxDynamicSharedMemorySize, SMEMSZ);

    // weight conversion (each: 8*1024*4096/8 = 4194304 granules)
    k_conv<<<16384, 256>>>(W1, w1h);
    k_conv<<<16384, 256>>>(W2, w2h);

    k_init<<<1, NT>>>();
    k_route<<<NTOK / 8, 256>>>(x, pe, pw, cw, ps, cs);
    k_scan<<<1, 1>>>();
    k_build<<<NTOK / 256, 256>>>();

    k_gemm<DC, DH, true><<<dim3(DH / BN, MAXTB), 128, SMEMSZ>>>(w1h, b1, nullptr);
    k_gemm<DH, DC, false><<<dim3(DC / BN, MAXTB), 128, SMEMSZ>>>(w2h, b2, out);
}

// round 7
// speedup vs baseline: 2.2847x; 1.0307x over previous
#include <cuda_runtime.h>
#include <cuda_fp16.h>
#include <cstdint>
#include <math.h>

#define BATCH 16
#define SEQ   512
#define DC    1024
#define DP    64
#define NT    8
#define DH    4096
#define NTOK  (BATCH*SEQ)

// ---- GEMM tiling: CTA 128(tokens) x 128(wcols) x 64(k), 4 warps of 64x64, fp16 m16n8k16 ----
#define BM 128
#define BN 128
#define BK 64
#define ASTRB 144                   // bytes per A row (128 data + 16 pad)
#define BSTRB 272                   // bytes per B row (256 data + 16 pad)
#define B_OFF (BM*ASTRB)            // 18432
#define STAGEB (B_OFF + BK*BSTRB)   // 35840
#define NSTAGE 3
#define SMEMSZ (NSTAGE*STAGEB)      // 107520  (x2 CTAs = 215 KB/SM)
#define MAXTB  72

// ---- scratch (static __device__: allocation-free) ----
__device__ int    g_tile_of[NTOK];
__device__ int    g_counts[NT];
__device__ int    g_offsets[NT];
__device__ int    g_perm[NTOK];
__device__ __half g_xh[(size_t)NTOK * DC];       // x rounded to half
__device__ __half g_h[(size_t)NTOK * DH];        // intermediate (permuted), half
__device__ __half g_w1h[(size_t)NT * DC * DH];   // W1 in half
__device__ __half g_w2h[(size_t)NT * DH * DC];   // W2 in half

// ================= helpers =================
__device__ __forceinline__ uint32_t smem_u32(const void* p) {
    uint32_t a;
    asm("{ .reg .u64 t; cvta.to.shared.u64 t, %1; cvt.u32.u64 %0, t; }" : "=r"(a) : "l"(p));
    return a;
}
__device__ __forceinline__ void cp_async16(uint32_t dst, const void* src) {
    asm volatile("cp.async.cg.shared.global [%0], [%1], 16;" :: "r"(dst), "l"(src));
}
__device__ __forceinline__ void cp_commit() { asm volatile("cp.async.commit_group;" ::: "memory"); }
__device__ __forceinline__ void cp_wait1()  { asm volatile("cp.async.wait_group 1;" ::: "memory"); }

__device__ __forceinline__ void ldsm4(uint32_t* r, uint32_t addr) {
    asm volatile("ldmatrix.sync.aligned.m8n8.x4.shared.b16 {%0,%1,%2,%3}, [%4];"
                 : "=r"(r[0]), "=r"(r[1]), "=r"(r[2]), "=r"(r[3]) : "r"(addr));
}
__device__ __forceinline__ void ldsm4t(uint32_t* r, uint32_t addr) {
    asm volatile("ldmatrix.sync.aligned.m8n8.x4.trans.shared.b16 {%0,%1,%2,%3}, [%4];"
                 : "=r"(r[0]), "=r"(r[1]), "=r"(r[2]), "=r"(r[3]) : "r"(addr));
}
__device__ __forceinline__ void mma16(float* c, const uint32_t* a, const uint32_t* b) {
    asm volatile(
        "mma.sync.aligned.m16n8k16.row.col.f32.f16.f16.f32 "
        "{%0,%1,%2,%3}, {%4,%5,%6,%7}, {%8,%9}, {%0,%1,%2,%3};\n"
        : "+f"(c[0]), "+f"(c[1]), "+f"(c[2]), "+f"(c[3])
        : "r"(a[0]), "r"(a[1]), "r"(a[2]), "r"(a[3]), "r"(b[0]), "r"(b[1]));
}

// ================= weight conversion (fp32 -> fp16, RN) =================
__global__ void k_conv(const float* __restrict__ src, __half* __restrict__ dst) {
    size_t i = (size_t)blockIdx.x * 256 + threadIdx.x;   // one 16B output granule
    const float4* s = (const float4*)src + i * 2;
    float4 v0 = s[0], v1 = s[1];
    __half2 h0 = __floats2half2_rn(v0.x, v0.y);
    __half2 h1 = __floats2half2_rn(v0.z, v0.w);
    __half2 h2 = __floats2half2_rn(v1.x, v1.y);
    __half2 h3 = __floats2half2_rn(v1.z, v1.w);
    uint4 o;
    o.x = *(uint32_t*)&h0; o.y = *(uint32_t*)&h1;
    o.z = *(uint32_t*)&h2; o.w = *(uint32_t*)&h3;
    ((uint4*)dst)[i] = o;
}

// ================= routing (tile_of + xh only; counts done in k_scanbuild) =================
__global__ void k_route(const float* __restrict__ x, const float* __restrict__ pe,
                        const float* __restrict__ pwp, const float* __restrict__ cwp,
                        const float* __restrict__ ps, const float* __restrict__ cs) {
    __shared__ float s_cs[NT * DC];
    __shared__ float s_ps[NT * DP];
    int tid = threadIdx.x;
    for (int i = tid; i < NT * DC; i += 256) {
        float v = cs[i];
        s_cs[i] = (v > 0.f) ? 1.f : ((v < 0.f) ? -1.f : 0.f);
    }
    for (int i = tid; i < NT * DP; i += 256) {
        float v = ps[i];
        s_ps[i] = (v > 0.f) ? 1.f : ((v < 0.f) ? -1.f : 0.f);
    }
    __syncthreads();

    int token = blockIdx.x * 8 + (tid >> 5);
    int lane  = tid & 31;
    const float* xr  = x  + (size_t)token * DC;
    const float* per = pe + (size_t)(token % SEQ) * DP;

    float ac[NT], ap[NT];
#pragma unroll
    for (int t = 0; t < NT; t++) { ac[t] = 0.f; ap[t] = 0.f; }
    for (int d = lane; d < DC; d += 32) {
        float xv = xr[d];
        g_xh[(size_t)token * DC + d] = __float2half_rn(xv);
#pragma unroll
        for (int t = 0; t < NT; t++) ac[t] += s_cs[t * DC + d] * xv;
    }
#pragma unroll
    for (int d = lane; d < DP; d += 32) {
        float pv = per[d];
#pragma unroll
        for (int t = 0; t < NT; t++) ap[t] += s_ps[t * DP + d] * pv;
    }
#pragma unroll
    for (int t = 0; t < NT; t++) {
        float v = ac[t];
#pragma unroll
        for (int o = 16; o; o >>= 1) v += __shfl_xor_sync(0xffffffffu, v, o);
        ac[t] = v;
        float w = ap[t];
#pragma unroll
        for (int o = 16; o; o >>= 1) w += __shfl_xor_sync(0xffffffffu, w, o);
        ap[t] = w;
    }
    if (lane == 0) {
        float pw = 1.f / (1.f + expf(-pwp[0]));
        float cw = 1.f / (1.f + expf(-cwp[0]));
        float tot = pw + cw;
        pw /= tot; cw /= tot;
        float best = -3.0e38f;
        int bi = 0;
#pragma unroll
        for (int t = 0; t < NT; t++) {
            float sc = pw * ap[t] + cw * ac[t];
            if (sc > best) { best = sc; bi = t; }
        }
        g_tile_of[token] = bi;
    }
}

// count + prefix + permutation in a single block (keeps gemm1 at launch index 4)
__global__ void k_scanbuild() {
    __shared__ int cnt[NT], offs[NT], cur[NT];
    int tid = threadIdx.x;
    if (tid < NT) cnt[tid] = 0;
    __syncthreads();
    for (int i = tid; i < NTOK; i += 256) atomicAdd(&cnt[g_tile_of[i]], 1);
    __syncthreads();
    if (tid == 0) {
        int acc = 0;
        for (int t = 0; t < NT; t++) {
            offs[t] = acc; cur[t] = 0;
            g_offsets[t] = acc; g_counts[t] = cnt[t];
            acc += cnt[t];
        }
    }
    __syncthreads();
    for (int i = tid; i < NTOK; i += 256) {
        int t = g_tile_of[i];
        int p = atomicAdd(&cur[t], 1);
        g_perm[offs[t] + p] = i;
    }
}

// ================= grouped GEMM: fp16 m16n8k16, cp.async 3-stage BK=64, ldmatrix A+B =================
template <int KD, int ND, bool FIRST>
__global__ void __launch_bounds__(128, 2)
k_gemm(const __half* __restrict__ Wh, const float* __restrict__ Bias, float* __restrict__ Out)
{
    extern __shared__ char dsm[];
    uint32_t sb = smem_u32(dsm);

    int tid = threadIdx.x, lane = tid & 31, wid = tid >> 5;
    int warp_m = wid & 1, warp_n = wid >> 1;          // 2 x 2 warps of 64x64
    int g = lane >> 2, tg = lane & 3;

    // ---- map blockIdx.y -> (tile, local token-block) ----
    int tb = blockIdx.y;
    int tile = -1, tloc = 0, acc = 0;
#pragma unroll
    for (int t = 0; t < NT; t++) {
        int nb = (g_counts[t] + BM - 1) >> 7;
        if (tile < 0 && tb < acc + nb) { tile = t; tloc = tb - acc; }
        acc += nb;
    }
    if (tile < 0) return;
    int cnt  = g_counts[tile];
    int off  = g_offsets[tile];
    int tok0 = tloc * BM;
    int n0   = blockIdx.x * BN;
    const __half* Wt = Wh + (size_t)tile * KD * ND;

    // ---- cp.async geometry ----
    // A: 8 granules/thread; granule q: row = (tid>>3)+16q, seg = tid&7 (16B within 128B row)
    const __half* aptr[8];
#pragma unroll
    for (int q = 0; q < 8; q++) {
        int r  = (tid >> 3) + 16 * q;
        int tk = tok0 + r; if (tk >= cnt) tk = cnt - 1;   // clamp; garbage rows masked later
        const __half* base = FIRST ? (g_xh + (size_t)g_perm[off + tk] * KD)
                                   : (g_h + (size_t)(off + tk) * KD);
        aptr[q] = base + (tid & 7) * 8;
    }
    uint32_t a_dst0 = (uint32_t)((tid >> 3) * ASTRB + (tid & 7) * 16);
    // B: 8 granules/thread; granule q: row = (tid>>4)+8q, seg = tid&15 (16B within 256B row)
    const __half* bptr0 = Wt + (size_t)(tid >> 4) * ND + n0 + (tid & 15) * 8;
    uint32_t b_dst0 = (uint32_t)(B_OFF + (tid >> 4) * BSTRB + (tid & 15) * 16);

    auto pf = [&](int j, int s) {
        uint32_t st = sb + (uint32_t)s * STAGEB;
        int k0 = j * BK;
#pragma unroll
        for (int q = 0; q < 8; q++)
            cp_async16(st + a_dst0 + (uint32_t)q * (16 * ASTRB), aptr[q] + k0);
        const __half* bs = bptr0 + (size_t)k0 * ND;
#pragma unroll
        for (int q = 0; q < 8; q++)
            cp_async16(st + b_dst0 + (uint32_t)q * (8 * BSTRB), bs + (size_t)q * 8 * ND);
    };

    // ---- fragment geometry (verified round-5 layout; strides updated) ----
    uint32_t a_frag = (uint32_t)((warp_m * 64 + (lane & 15)) * ASTRB + (lane >> 4) * 16);
    uint32_t b_frag = (uint32_t)(B_OFF + ((lane & 7) + ((lane >> 3) & 1) * 8) * BSTRB
                                 + (warp_n * 64 + (lane >> 4) * 8) * 2);

    float accf[4][8][4];
#pragma unroll
    for (int mt = 0; mt < 4; mt++)
#pragma unroll
        for (int j = 0; j < 8; j++)
#pragma unroll
            for (int e = 0; e < 4; e++) accf[mt][j][e] = 0.f;

    constexpr int NCH = KD / BK;

    pf(0, 0); cp_commit();
    pf(1, 1); cp_commit();

    int s = 0;
    for (int i = 0; i < NCH; i++) {
        cp_wait1();                 // chunk i resident (only i+1 may pend)
        __syncthreads();            // visible to all; stage (i+2)%3 free of readers

        if (i + 2 < NCH) pf(i + 2, (i + 2) % NSTAGE);
        cp_commit();                // commit every iter: exact group accounting

        uint32_t stg = sb + (uint32_t)s * STAGEB;
#pragma unroll
        for (int ks = 0; ks < 4; ks++) {
            uint32_t af[4][4], bf[4][4];
#pragma unroll
            for (int mt = 0; mt < 4; mt++)
                ldsm4(af[mt], stg + a_frag + (uint32_t)(mt * 16 * ASTRB + ks * 32));
#pragma unroll
            for (int nt = 0; nt < 4; nt++)
                ldsm4t(bf[nt], stg + b_frag + (uint32_t)(ks * 16 * BSTRB + nt * 32));
#pragma unroll
            for (int mt = 0; mt < 4; mt++)
#pragma unroll
                for (int nt = 0; nt < 4; nt++) {
                    mma16(accf[mt][nt * 2 + 0], af[mt], &bf[nt][0]);
                    mma16(accf[mt][nt * 2 + 1], af[mt], &bf[nt][2]);
                }
        }
        s++; if (s == NSTAGE) s = 0;
    }

    // ---- epilogue ----
#pragma unroll
    for (int j = 0; j < 8; j++) {
        int col = n0 + warp_n * 64 + j * 8 + tg * 2;
        float2 bv = *(const float2*)&Bias[(size_t)tile * ND + col];
#pragma unroll
        for (int mt = 0; mt < 4; mt++) {
            int rbase = tok0 + warp_m * 64 + mt * 16 + g;
#pragma unroll
            for (int h = 0; h < 2; h++) {
                int row = rbase + h * 8;
                if (row < cnt) {
                    float v0 = accf[mt][j][h * 2 + 0] + bv.x;
                    float v1 = accf[mt][j][h * 2 + 1] + bv.y;
                    if (FIRST) {
                        v0 = 0.5f * v0 * (1.f + erff(v0 * 0.70710678118654752f));
                        v1 = 0.5f * v1 * (1.f + erff(v1 * 0.70710678118654752f));
                        __half2 hv = __floats2half2_rn(v0, v1);
                        *(__half2*)&g_h[(size_t)(off + row) * ND + col] = hv;
                    } else {
                        *(float2*)&Out[(size_t)g_perm[off + row] * ND + col] = make_float2(v0, v1);
                    }
                }
            }
        }
    }
}

extern "C" void kernel_launch(void* const* d_in, const int* in_sizes, int n_in,
                              void* d_out, int out_size) {
    const float* x  = (const float*)d_in[0];
    const float* pe = (const float*)d_in[1];
    const float* pw = (const float*)d_in[2];
    const float* cw = (const float*)d_in[3];
    const float* ps = (const float*)d_in[4];
    const float* cs = (const float*)d_in[5];
    const float* W1 = (const float*)d_in[6];
    const float* b1 = (const float*)d_in[7];
    const float* W2 = (const float*)d_in[8];
    const float* b2 = (const float*)d_in[9];
    float* out = (float*)d_out;

    static __half* w1h = nullptr;
    static __half* w2h = nullptr;
    static cudaStream_t side = nullptr;
    static cudaEvent_t evFork = nullptr, evJ1 = nullptr, evJ2 = nullptr;
    if (!side) {
        cudaGetSymbolAddress((void**)&w1h, g_w1h);   // address queries only, no alloc
        cudaGetSymbolAddress((void**)&w2h, g_w2h);
        cudaStreamCreateWithFlags(&side, cudaStreamNonBlocking);
        cudaEventCreateWithFlags(&evFork, cudaEventDisableTiming);
        cudaEventCreateWithFlags(&evJ1,   cudaEventDisableTiming);
        cudaEventCreateWithFlags(&evJ2,   cudaEventDisableTiming);
        cudaFuncSetAttribute(k_gemm<DC, DH, true>,  cudaFuncAttributeMaxDynamicSharedMemorySize, SMEMSZ);
        cudaFuncSetAttribute(k_gemm<DH, DC, false>, cudaFuncAttributeMaxDynamicSharedMemorySize, SMEMSZ);
    }

    // fork side stream from the origin stream (capture-legal cross-stream pattern)
    cudaEventRecord(evFork, 0);
    cudaStreamWaitEvent(side, evFork, 0);

    // #1: convert W1 on side stream (overlaps route+scanbuild)
    k_conv<<<16384, 256, 0, side>>>(W1, w1h);
    cudaEventRecord(evJ1, side);

    // #2, #3 on main stream
    k_route<<<NTOK / 8, 256>>>(x, pe, pw, cw, ps, cs);
    k_scanbuild<<<1, 256>>>();

    // #4: GEMM1 (profiled launch) — needs routing + W1h
    cudaStreamWaitEvent(0, evJ1, 0);
    k_gemm<DC, DH, true><<<dim3(DH / BN, MAXTB), 128, SMEMSZ>>>(w1h, b1, nullptr);

    // #5: convert W2 on side stream (overlaps GEMM1)
    k_conv<<<16384, 256, 0, side>>>(W2, w2h);
    cudaEventRecord(evJ2, side);

    // #6: GEMM2 — needs g_h + W2h
    cudaStreamWaitEvent(0, evJ2, 0);
    k_gemm<DH, DC, false><<<dim3(DC / BN, MAXTB), 128, SMEMSZ>>>(w2h, b2, out);
}